// round 5
// baseline (speedup 1.0000x reference)
#include <cuda_runtime.h>
#include <cstdint>

#define BSZ    256
#define FEAT   128
#define KP1    4097
#define PAD    4100
#define NDATA  500000
#define SDIM   1024
#define TDIM   2048
#define MEMELEMS 64000000
#define TOTAL  (BSZ * KP1)
#define EPSF   1e-7f
#define MPN    (4096.0f / 500000.0f)
#define N4     15999999
#define LOSS_BLOCKS 1280
#define KSPLIT 8
#define FULLM  0xffffffffu

__device__ float g_es[BSZ * FEAT];
__device__ float g_et[BSZ * FEAT];
__device__ float g_part_s[KSPLIT * BSZ * FEAT];
__device__ float g_part_t[KSPLIT * BSZ * FEAT];
__device__ float g_out_s[BSZ * PAD];
__device__ float g_out_t[BSZ * PAD];
__device__ float g_sums[3];
__device__ int   g_ticket;
__device__ int   g_rtcnt[128];   // zero-init; self-resetting per replay

// ---------------------------------------------------------------- embed (split-K + fused normalize)
// 1024 blocks: bid<512 s-side, else t-side. id>>3 = rowtile (4 rows), id&7 = ksplit.
// Last ksplit block per rowtile (via ticket) sums partials, adds bias, L2-normalizes.
__global__ __launch_bounds__(128) void embed_kernel(const float* __restrict__ f_s,
                                                    const float* __restrict__ f_t,
                                                    const float* __restrict__ W_s,
                                                    const float* __restrict__ W_t,
                                                    const float* __restrict__ b_s,
                                                    const float* __restrict__ b_t) {
    if (blockIdx.x == 0 && threadIdx.x == 0) {
        g_sums[0] = 0.f; g_sums[1] = 0.f; g_sums[2] = 0.f; g_ticket = 0;
    }
    __shared__ float fsh[4 * 256];
    __shared__ float sh[4];
    __shared__ int  sh_last;
    const int bid = blockIdx.x;
    const bool is_t = bid >= 512;
    const int id = is_t ? bid - 512 : bid;
    const int rt = id >> 3;
    const int ks = id & 7;
    const int Kd = is_t ? TDIM : SDIM;
    const int kchunk = Kd / KSPLIT;
    const int k0 = ks * kchunk;
    const float* f = is_t ? f_t : f_s;
    const float* W = is_t ? W_t : W_s;
    float* part = is_t ? g_part_t : g_part_s;
    const int rows0 = rt * 4;
    const int t = threadIdx.x;

    #pragma unroll
    for (int r = 0; r < 4; ++r)
        for (int k = t; k < kchunk; k += 128)
            fsh[r * 256 + k] = f[(rows0 + r) * Kd + k0 + k];
    __syncthreads();

    float a0 = 0.f, a1 = 0.f, a2 = 0.f, a3 = 0.f;
    const float* Wp = W + (size_t)k0 * FEAT + t;
    #pragma unroll 8
    for (int k = 0; k < kchunk; ++k) {
        float w = Wp[(size_t)k * FEAT];
        a0 += fsh[k] * w;
        a1 += fsh[256 + k] * w;
        a2 += fsh[512 + k] * w;
        a3 += fsh[768 + k] * w;
    }
    part[(ks * BSZ + rows0 + 0) * FEAT + t] = a0;
    part[(ks * BSZ + rows0 + 1) * FEAT + t] = a1;
    part[(ks * BSZ + rows0 + 2) * FEAT + t] = a2;
    part[(ks * BSZ + rows0 + 3) * FEAT + t] = a3;

    // ticket: last ksplit block of this rowtile does the reduction+normalize
    __threadfence();
    __syncthreads();
    const int cidx_ = (is_t ? 64 : 0) + rt;
    if (t == 0) sh_last = (atomicAdd(&g_rtcnt[cidx_], 1) == KSPLIT - 1);
    __syncthreads();
    if (!sh_last) return;
    __threadfence();

    const float* bias = is_t ? b_t : b_s;
    float* out = is_t ? g_et : g_es;
    const int lane = t & 31, w_ = t >> 5;
    #pragma unroll
    for (int r = 0; r < 4; ++r) {
        float v = bias[t];
        #pragma unroll
        for (int kk = 0; kk < KSPLIT; ++kk)
            v += part[(kk * BSZ + rows0 + r) * FEAT + t];
        float sq = v * v;
        #pragma unroll
        for (int o = 16; o; o >>= 1) sq += __shfl_xor_sync(FULLM, sq, o);
        if (lane == 0) sh[w_] = sq;
        __syncthreads();
        float tot = sh[0] + sh[1] + sh[2] + sh[3];
        __syncthreads();
        out[(rows0 + r) * FEAT + t] = v / sqrtf(tot);
    }
    if (t == 0) g_rtcnt[cidx_] = 0;   // self-reset for next graph replay
}

// ---------------------------------------------------------------- NCE: row-sorted gather + dot + exp
// Each warp owns 32 consecutive tasks (spanning at most 2 batch rows b0,b0+1).
// Tasks processed in ascending memory-row order for chip-wide L2 locality.
__global__ __launch_bounds__(256) void nce_kernel(const int* __restrict__ cidx,
                                                  const float* __restrict__ m1,
                                                  const float* __restrict__ m2) {
    const int lane = threadIdx.x & 31;
    const int wInB = threadIdx.x >> 5;
    const int wid  = (blockIdx.x * blockDim.x + threadIdx.x) >> 5;
    const int t0   = wid * 32;
    const int b0   = t0 / KP1;
    const int k0   = t0 - b0 * KP1;
    const int b1   = (b0 + 1 < BSZ) ? b0 + 1 : b0;

    // this lane's task
    int row = __ldg(cidx + t0 + lane);
    int key = (row << 5) | lane;          // unique keys (row < 2^19)

    // bitonic sort ascending across the warp
    #pragma unroll
    for (int sz = 2; sz <= 32; sz <<= 1) {
        #pragma unroll
        for (int st = sz >> 1; st > 0; st >>= 1) {
            int other = __shfl_xor_sync(FULLM, key, st);
            bool dirAsc = ((lane & sz) == 0);
            bool lower  = ((lane & st) == 0);
            bool takeOther = (other < key) == (dirAsc == lower);
            key = takeOther ? other : key;
        }
    }

    const float4 es4a = *((const float4*)(g_es + b0 * FEAT) + lane);
    const float4 et4a = *((const float4*)(g_et + b0 * FEAT) + lane);
    const float4 es4b = *((const float4*)(g_es + b1 * FEAT) + lane);
    const float4 et4b = *((const float4*)(g_et + b1 * FEAT) + lane);

    float sumT = 0.f, sumS = 0.f;

    #pragma unroll 1
    for (int g = 0; g < 8; ++g) {
        int rows[4], bs[4], ksj[4];
        bool wrap[4];
        #pragma unroll
        for (int j = 0; j < 4; ++j) {
            int kk = __shfl_sync(FULLM, key, g * 4 + j);
            rows[j] = kk >> 5;
            int lj  = kk & 31;
            int kl  = k0 + lj;
            wrap[j] = (kl >= KP1);
            ksj[j]  = wrap[j] ? kl - KP1 : kl;
            bs[j]   = wrap[j] ? b1 : b0;
        }
        float4 A[4], C[4];
        #pragma unroll
        for (int j = 0; j < 4; ++j) {
            A[j] = __ldg((const float4*)m1 + (size_t)rows[j] * 32 + lane);
            C[j] = __ldg((const float4*)m2 + (size_t)rows[j] * 32 + lane);
        }
        float dt[4], ds[4];
        #pragma unroll
        for (int j = 0; j < 4; ++j) {
            float4 eT = wrap[j] ? et4b : et4a;
            float4 eS = wrap[j] ? es4b : es4a;
            dt[j] = A[j].x * eT.x + A[j].y * eT.y + A[j].z * eT.z + A[j].w * eT.w;
            ds[j] = C[j].x * eS.x + C[j].y * eS.y + C[j].z * eS.z + C[j].w * eS.w;
        }
        #pragma unroll
        for (int o = 16; o; o >>= 1) {
            #pragma unroll
            for (int j = 0; j < 4; ++j) {
                dt[j] += __shfl_xor_sync(FULLM, dt[j], o);
                ds[j] += __shfl_xor_sync(FULLM, ds[j], o);
            }
        }
        if (lane == 0) {
            #pragma unroll
            for (int j = 0; j < 4; ++j) {
                float ot = __expf(dt[j] * (1.0f / 0.07f));
                float os = __expf(ds[j] * (1.0f / 0.07f));
                g_out_t[bs[j] * PAD + ksj[j]] = ot;
                g_out_s[bs[j] * PAD + ksj[j]] = os;
                sumT += ot; sumS += os;
            }
        }
    }

    __shared__ float shT[8], shS[8];
    if (lane == 0) { shT[wInB] = sumT; shS[wInB] = sumS; }
    __syncthreads();
    if (threadIdx.x == 0) {
        float aT = 0.f, aS = 0.f;
        #pragma unroll
        for (int i = 0; i < 8; ++i) { aT += shT[i]; aS += shS[i]; }
        atomicAdd(&g_sums[0], aT);
        atomicAdd(&g_sums[1], aS);
    }
}

// ---------------------------------------------------------------- copy + loss fused
// bid < LOSS_BLOCKS: loss (incl. out[0] finalize via ticket). Else: streaming copy.
__global__ __launch_bounds__(256) void copyloss_kernel(const float* __restrict__ m1,
                                                       const float* __restrict__ m2,
                                                       float* __restrict__ out) {
    const int bid = blockIdx.x;
    if (bid < LOSS_BLOCKS) {
        const int b = bid / 5;
        const int k = ((bid % 5) * 256 + threadIdx.x) * 4;
        const float invZt = (float)TOTAL / ((float)NDATA * g_sums[0]);
        const float invZs = (float)TOTAL / ((float)NDATA * g_sums[1]);
        float acc = 0.f;
        if (k < KP1) {
            float4 vs = *((const float4*)(g_out_s + b * PAD + k));
            float4 vt = *((const float4*)(g_out_t + b * PAD + k));
            float xs[4] = {vs.x, vs.y, vs.z, vs.w};
            float xt[4] = {vt.x, vt.y, vt.z, vt.w};
            #pragma unroll
            for (int c = 0; c < 4; ++c) {
                if (k + c < KP1) {
                    float xS = xs[c] * invZs;
                    float xT = xt[c] * invZt;
                    if (k + c == 0) {
                        acc += logf(xS / (xS + MPN + EPSF)) + logf(xT / (xT + MPN + EPSF));
                    } else {
                        acc -= logf(1.0f + (xS + EPSF) * (1.0f / MPN));
                        acc -= logf(1.0f + (xT + EPSF) * (1.0f / MPN));
                    }
                }
            }
        }
        #pragma unroll
        for (int o = 16; o; o >>= 1) acc += __shfl_xor_sync(FULLM, acc, o);
        __shared__ float sh[8];
        const int lane = threadIdx.x & 31, w_ = threadIdx.x >> 5;
        if (lane == 0) sh[w_] = acc;
        __syncthreads();
        if (threadIdx.x == 0) {
            float tot = 0.f;
            #pragma unroll
            for (int i = 0; i < 8; ++i) tot += sh[i];
            atomicAdd(&g_sums[2], tot);
            __threadfence();
            int tk = atomicAdd(&g_ticket, 1);
            if (tk == LOSS_BLOCKS - 1)
                out[0] = -g_sums[2] / (float)BSZ;
        }
        return;
    }

    // ---------------- copy role ----------------
    const int tid = (bid - LOSS_BLOCKS) * 256 + threadIdx.x;
    const int T = 15625 * 256;   // 4,000,000
    float4* o1b = (float4*)(out + 4);
    float4* o2b = (float4*)(out + 4 + MEMELEMS);
    #pragma unroll
    for (int s = 0; s < 4; ++s) {
        const int i = tid + s * T;
        if (i < N4) {
            float  h1 = __ldg(m1 + 3 + 4 * i);
            float4 v1 = __ldg((const float4*)(m1 + 4 + 4 * i));
            float  h2 = __ldg(m2 + 3 + 4 * i);
            float4 v2 = __ldg((const float4*)(m2 + 4 + 4 * i));
            o1b[i] = make_float4(h1, v1.x, v1.y, v1.z);
            o2b[i] = make_float4(h2, v2.x, v2.y, v2.z);
        }
    }
    if (tid == 0) {
        out[1] = m1[0]; out[2] = m1[1]; out[3] = m1[2];
        out[MEMELEMS] = m1[MEMELEMS - 1];
        out[1 + MEMELEMS] = m2[0]; out[2 + MEMELEMS] = m2[1]; out[3 + MEMELEMS] = m2[2];
        out[2 * MEMELEMS] = m2[MEMELEMS - 1];
    }
}

// ---------------------------------------------------------------- scatter update (after copy)
__global__ __launch_bounds__(128) void update_kernel(const int* __restrict__ idx,
                                                     const float* __restrict__ m1,
                                                     const float* __restrict__ m2,
                                                     float* __restrict__ out) {
    const int b = blockIdx.x;
    const int t = threadIdx.x;
    float* o1 = out + 1;
    float* o2 = out + 1 + MEMELEMS;
    const int row = __ldg(idx + b);
    const size_t off = (size_t)row * FEAT + t;
    float v1 = __ldg(m1 + off) * 0.5f + g_es[b * FEAT + t] * 0.5f;
    float v2 = __ldg(m2 + off) * 0.5f + g_et[b * FEAT + t] * 0.5f;
    float s1 = v1 * v1, s2 = v2 * v2;
    #pragma unroll
    for (int o = 16; o; o >>= 1) {
        s1 += __shfl_xor_sync(FULLM, s1, o);
        s2 += __shfl_xor_sync(FULLM, s2, o);
    }
    __shared__ float sh1[4], sh2[4];
    const int lane = t & 31, w_ = t >> 5;
    if (lane == 0) { sh1[w_] = s1; sh2[w_] = s2; }
    __syncthreads();
    float t1 = sh1[0] + sh1[1] + sh1[2] + sh1[3];
    float t2 = sh2[0] + sh2[1] + sh2[2] + sh2[3];
    o1[off] = v1 / sqrtf(t1);
    o2[off] = v2 / sqrtf(t2);
}

// ---------------------------------------------------------------- launch
extern "C" void kernel_launch(void* const* d_in, const int* in_sizes, int n_in,
                              void* d_out, int out_size) {
    const float* f_s  = (const float*)d_in[0];
    const float* f_t  = (const float*)d_in[1];
    const int*   idx  = (const int*)  d_in[2];
    const int*   cidx = (const int*)  d_in[3];
    const float* W_s  = (const float*)d_in[4];
    const float* b_s  = (const float*)d_in[5];
    const float* W_t  = (const float*)d_in[6];
    const float* b_t  = (const float*)d_in[7];
    const float* m1   = (const float*)d_in[8];
    const float* m2   = (const float*)d_in[9];
    float* out = (float*)d_out;

    embed_kernel<<<1024, 128>>>(f_s, f_t, W_s, W_t, b_s, b_t);
    nce_kernel<<<4097, 256>>>(cidx, m1, m2);
    copyloss_kernel<<<LOSS_BLOCKS + 15625, 256>>>(m1, m2, out);
    update_kernel<<<BSZ, 128>>>(idx, m1, m2, out);
}

// round 6
// speedup vs baseline: 1.0503x; 1.0503x over previous
#include <cuda_runtime.h>
#include <cstdint>

#define BSZ    256
#define FEAT   128
#define KP1    4097
#define NDATA  500000
#define SDIM   1024
#define TDIM   2048
#define MEMELEMS 64000000
#define TOTAL  (BSZ * KP1)        // 1,048,832
#define EPSF   1e-7f
#define MPN    (4096.0f / 500000.0f)
#define N4     15999999
#define KSPLIT 8
#define FULLM  0xffffffffu

#define NBUCK  245                 // row >> 11 : 0..244
#define BINS   (NBUCK * 256)       // 62720
#define CAP    96
#define LOSS_BLOCKS (BINS / 8)     // 7840
#define NCE_GRID 592

__device__ float g_es[BSZ * FEAT];
__device__ float g_et[BSZ * FEAT];
__device__ float g_part_s[KSPLIT * BSZ * FEAT];
__device__ float g_part_t[KSPLIT * BSZ * FEAT];
__device__ float g_sums[3];
__device__ int   g_ticket;
__device__ int   g_binctr;
__device__ int   g_cnt[BINS];
__device__ unsigned g_tasklist[BINS * CAP];   // (row<<13)|k
__device__ float g_outS[BINS * CAP];
__device__ float g_outT[BINS * CAP];

// ---------------------------------------------------------------- embed partial (split-K) + counter zeroing
// 1024 blocks x 128 thr. bid<512 s-side, else t-side. Also zeroes g_cnt / globals.
__global__ __launch_bounds__(128) void embed_partial(const float* __restrict__ f_s,
                                                     const float* __restrict__ f_t,
                                                     const float* __restrict__ W_s,
                                                     const float* __restrict__ W_t) {
    // zero bins: blocks 0..511 cover 65536 slots >= BINS
    {
        const int z = blockIdx.x * 128 + threadIdx.x;
        if (blockIdx.x < 512 && z < BINS) g_cnt[z] = 0;
        if (z == 0) { g_sums[0] = 0.f; g_sums[1] = 0.f; g_sums[2] = 0.f; g_ticket = 0; g_binctr = 0; }
    }
    __shared__ float fsh[4 * 256];
    const int bid = blockIdx.x;
    const bool is_t = bid >= 512;
    const int id = is_t ? bid - 512 : bid;
    const int rt = id >> 3;
    const int ks = id & 7;
    const int Kd = is_t ? TDIM : SDIM;
    const int kchunk = Kd / KSPLIT;
    const int k0 = ks * kchunk;
    const float* f = is_t ? f_t : f_s;
    const float* W = is_t ? W_t : W_s;
    float* part = is_t ? g_part_t : g_part_s;
    const int rows0 = rt * 4;
    const int t = threadIdx.x;

    #pragma unroll
    for (int r = 0; r < 4; ++r)
        for (int k = t; k < kchunk; k += 128)
            fsh[r * 256 + k] = f[(rows0 + r) * Kd + k0 + k];
    __syncthreads();

    float a0 = 0.f, a1 = 0.f, a2 = 0.f, a3 = 0.f;
    const float* Wp = W + (size_t)k0 * FEAT + t;
    #pragma unroll 8
    for (int k = 0; k < kchunk; ++k) {
        float w = Wp[(size_t)k * FEAT];
        a0 += fsh[k] * w;
        a1 += fsh[256 + k] * w;
        a2 += fsh[512 + k] * w;
        a3 += fsh[768 + k] * w;
    }
    part[(ks * BSZ + rows0 + 0) * FEAT + t] = a0;
    part[(ks * BSZ + rows0 + 1) * FEAT + t] = a1;
    part[(ks * BSZ + rows0 + 2) * FEAT + t] = a2;
    part[(ks * BSZ + rows0 + 3) * FEAT + t] = a3;
}

// ---------------------------------------------------------------- normalize + scatter (fused launch)
// bid<512: normalize row (bid<256 s, else t). bid>=512: scatter tasks into bins.
__global__ __launch_bounds__(128) void norm_scatter(const float* __restrict__ b_s,
                                                    const float* __restrict__ b_t,
                                                    const int* __restrict__ cidx) {
    const int bid = blockIdx.x;
    const int t = threadIdx.x;
    if (bid < 512) {
        const bool is_t = bid >= 256;
        const int row = is_t ? bid - 256 : bid;
        const float* part = is_t ? g_part_t : g_part_s;
        const float* bias = is_t ? b_t : b_s;
        float* out = is_t ? g_et : g_es;

        float v = bias[t];
        #pragma unroll
        for (int ks = 0; ks < KSPLIT; ++ks)
            v += part[(ks * BSZ + row) * FEAT + t];

        float sq = v * v;
        #pragma unroll
        for (int o = 16; o; o >>= 1) sq += __shfl_xor_sync(FULLM, sq, o);
        __shared__ float sh[4];
        const int lane = t & 31, w_ = t >> 5;
        if (lane == 0) sh[w_] = sq;
        __syncthreads();
        float tot = sh[0] + sh[1] + sh[2] + sh[3];
        out[row * FEAT + t] = v / sqrtf(tot);
        return;
    }
    // scatter role: 1024 blocks x 128 = 131072 threads, 8 tasks each
    const int tid = (bid - 512) * 128 + t;
    #pragma unroll 1
    for (int i = tid; i < TOTAL; i += 1024 * 128) {
        const unsigned row = (unsigned)__ldg(cidx + i);
        const int b = i / KP1;
        const int k = i - b * KP1;
        const int bin = (int)(row >> 11) * 256 + b;
        const int pos = atomicAdd(&g_cnt[bin], 1);
        if (pos < CAP)
            g_tasklist[(size_t)bin * CAP + pos] = (row << 13) | (unsigned)k;
    }
}

// ---------------------------------------------------------------- NCE: persistent, ordered bin consumption
__global__ __launch_bounds__(256) void nce_kernel(const float* __restrict__ m1,
                                                  const float* __restrict__ m2) {
    const int lane = threadIdx.x & 31;
    const int wInB = threadIdx.x >> 5;
    float sumT = 0.f, sumS = 0.f;

    for (;;) {
        int bin0 = 0;
        if (lane == 0) bin0 = atomicAdd(&g_binctr, 2);
        bin0 = __shfl_sync(FULLM, bin0, 0);
        if (bin0 >= BINS) break;

        #pragma unroll 1
        for (int bi = 0; bi < 2; ++bi) {
            const int bin = bin0 + bi;
            if (bin >= BINS) break;
            int n = __ldg(&g_cnt[bin]);
            if (n <= 0) continue;
            if (n > CAP) n = CAP;
            const int b = bin & 255;
            const float4 es4 = *((const float4*)(g_es + b * FEAT) + lane);
            const float4 et4 = *((const float4*)(g_et + b * FEAT) + lane);
            const unsigned* tl = g_tasklist + (size_t)bin * CAP;

            #pragma unroll 1
            for (int i0 = 0; i0 < n; i0 += 4) {
                const int m = min(4, n - i0);
                unsigned rec[4];
                int rows[4];
                #pragma unroll
                for (int j = 0; j < 4; ++j) {
                    rec[j] = __ldg(tl + i0 + ((j < m) ? j : m - 1));
                    rows[j] = (int)(rec[j] >> 13);
                }
                float4 A[4], C[4];
                #pragma unroll
                for (int j = 0; j < 4; ++j) {
                    A[j] = __ldg((const float4*)m1 + (size_t)rows[j] * 32 + lane);
                    C[j] = __ldg((const float4*)m2 + (size_t)rows[j] * 32 + lane);
                }
                float dt[4], ds[4];
                #pragma unroll
                for (int j = 0; j < 4; ++j) {
                    dt[j] = A[j].x * et4.x + A[j].y * et4.y + A[j].z * et4.z + A[j].w * et4.w;
                    ds[j] = C[j].x * es4.x + C[j].y * es4.y + C[j].z * es4.z + C[j].w * es4.w;
                }
                #pragma unroll
                for (int o = 16; o; o >>= 1) {
                    #pragma unroll
                    for (int j = 0; j < 4; ++j) {
                        dt[j] += __shfl_xor_sync(FULLM, dt[j], o);
                        ds[j] += __shfl_xor_sync(FULLM, ds[j], o);
                    }
                }
                if (lane == 0) {
                    #pragma unroll
                    for (int j = 0; j < 4; ++j) {
                        if (j < m) {
                            float ot = __expf(dt[j] * (1.0f / 0.07f));
                            float os = __expf(ds[j] * (1.0f / 0.07f));
                            g_outT[(size_t)bin * CAP + i0 + j] = ot;
                            g_outS[(size_t)bin * CAP + i0 + j] = os;
                            sumT += ot; sumS += os;
                        }
                    }
                }
            }
        }
    }

    __shared__ float shT[8], shS[8];
    if (lane == 0) { shT[wInB] = sumT; shS[wInB] = sumS; }
    __syncthreads();
    if (threadIdx.x == 0) {
        float aT = 0.f, aS = 0.f;
        #pragma unroll
        for (int i = 0; i < 8; ++i) { aT += shT[i]; aS += shS[i]; }
        atomicAdd(&g_sums[0], aT);
        atomicAdd(&g_sums[1], aS);
    }
}

// ---------------------------------------------------------------- memory copy-out (unchanged, proven 6.7+ TB/s)
__global__ __launch_bounds__(256) void copy_kernel(const float* __restrict__ m1,
                                                   const float* __restrict__ m2,
                                                   float* __restrict__ out) {
    const int tid = blockIdx.x * blockDim.x + threadIdx.x;
    const int T = gridDim.x * blockDim.x;   // 4,000,000
    float4* o1b = (float4*)(out + 4);
    float4* o2b = (float4*)(out + 4 + MEMELEMS);
    #pragma unroll
    for (int s = 0; s < 4; ++s) {
        const int i = tid + s * T;
        if (i < N4) {
            float  h1 = __ldg(m1 + 3 + 4 * i);
            float4 v1 = __ldg((const float4*)(m1 + 4 + 4 * i));
            float  h2 = __ldg(m2 + 3 + 4 * i);
            float4 v2 = __ldg((const float4*)(m2 + 4 + 4 * i));
            o1b[i] = make_float4(h1, v1.x, v1.y, v1.z);
            o2b[i] = make_float4(h2, v2.x, v2.y, v2.z);
        }
    }
    if (tid == 0) {
        out[1] = m1[0]; out[2] = m1[1]; out[3] = m1[2];
        out[MEMELEMS] = m1[MEMELEMS - 1];
        out[1 + MEMELEMS] = m2[0]; out[2 + MEMELEMS] = m2[1]; out[3 + MEMELEMS] = m2[2];
        out[2 * MEMELEMS] = m2[MEMELEMS - 1];
    }
}

// ---------------------------------------------------------------- loss (bin layout) + update + finalize
// bid < LOSS_BLOCKS: loss, warp per bin. bid >= LOSS_BLOCKS: update row.
__global__ __launch_bounds__(256) void lossup_kernel(const int* __restrict__ idx,
                                                     const float* __restrict__ m1,
                                                     const float* __restrict__ m2,
                                                     float* __restrict__ out) {
    const int bid = blockIdx.x;
    if (bid < LOSS_BLOCKS) {
        const int lane = threadIdx.x & 31;
        const int wInB = threadIdx.x >> 5;
        const int bin = bid * 8 + wInB;
        const float invZt = (float)TOTAL / ((float)NDATA * g_sums[0]);
        const float invZs = (float)TOTAL / ((float)NDATA * g_sums[1]);
        float acc = 0.f;
        int n = min(__ldg(&g_cnt[bin]), CAP);
        for (int i = lane; i < n; i += 32) {
            const unsigned rec = g_tasklist[(size_t)bin * CAP + i];
            const int k = (int)(rec & 8191u);
            float xS = g_outS[(size_t)bin * CAP + i] * invZs;
            float xT = g_outT[(size_t)bin * CAP + i] * invZt;
            if (k == 0) {
                acc += logf(xS / (xS + MPN + EPSF)) + logf(xT / (xT + MPN + EPSF));
            } else {
                acc -= logf(1.0f + (xS + EPSF) * (1.0f / MPN));
                acc -= logf(1.0f + (xT + EPSF) * (1.0f / MPN));
            }
        }
        #pragma unroll
        for (int o = 16; o; o >>= 1) acc += __shfl_xor_sync(FULLM, acc, o);
        __shared__ float sh[8];
        if (lane == 0) sh[wInB] = acc;
        __syncthreads();
        if (threadIdx.x == 0) {
            float tot = 0.f;
            #pragma unroll
            for (int i = 0; i < 8; ++i) tot += sh[i];
            atomicAdd(&g_sums[2], tot);
            __threadfence();
            int tk = atomicAdd(&g_ticket, 1);
            if (tk == LOSS_BLOCKS - 1)
                out[0] = -g_sums[2] / (float)BSZ;
        }
        return;
    }

    // update role
    const int b = bid - LOSS_BLOCKS;
    const int t = threadIdx.x;
    if (t >= 128) return;
    float* o1 = out + 1;
    float* o2 = out + 1 + MEMELEMS;
    const int row = __ldg(idx + b);
    const size_t off = (size_t)row * FEAT + t;
    float v1 = __ldg(m1 + off) * 0.5f + g_es[b * FEAT + t] * 0.5f;
    float v2 = __ldg(m2 + off) * 0.5f + g_et[b * FEAT + t] * 0.5f;
    float s1 = v1 * v1, s2 = v2 * v2;
    #pragma unroll
    for (int o = 16; o; o >>= 1) {
        s1 += __shfl_xor_sync(FULLM, s1, o);
        s2 += __shfl_xor_sync(FULLM, s2, o);
    }
    __shared__ float sh1[4], sh2[4];
    const int lane = t & 31, w_ = t >> 5;
    if (lane == 0) { sh1[w_] = s1; sh2[w_] = s2; }
    __syncthreads();
    float t1 = sh1[0] + sh1[1] + sh1[2] + sh1[3];
    float t2 = sh2[0] + sh2[1] + sh2[2] + sh2[3];
    o1[off] = v1 / sqrtf(t1);
    o2[off] = v2 / sqrtf(t2);
}

// ---------------------------------------------------------------- launch
extern "C" void kernel_launch(void* const* d_in, const int* in_sizes, int n_in,
                              void* d_out, int out_size) {
    const float* f_s  = (const float*)d_in[0];
    const float* f_t  = (const float*)d_in[1];
    const int*   idx  = (const int*)  d_in[2];
    const int*   cidx = (const int*)  d_in[3];
    const float* W_s  = (const float*)d_in[4];
    const float* b_s  = (const float*)d_in[5];
    const float* W_t  = (const float*)d_in[6];
    const float* b_t  = (const float*)d_in[7];
    const float* m1   = (const float*)d_in[8];
    const float* m2   = (const float*)d_in[9];
    float* out = (float*)d_out;

    embed_partial<<<1024, 128>>>(f_s, f_t, W_s, W_t);
    norm_scatter<<<1536, 128>>>(b_s, b_t, cidx);
    nce_kernel<<<NCE_GRID, 256>>>(m1, m2);
    copy_kernel<<<15625, 256>>>(m1, m2, out);
    lossup_kernel<<<LOSS_BLOCKS + BSZ, 256>>>(idx, m1, m2, out);
}